// round 15
// baseline (speedup 1.0000x reference)
#include <cuda_runtime.h>
#include <cuda_fp16.h>
#include <math.h>
#include <stdint.h>

#define B_TOT 65536
#define DH    256
#define BM    128
#define THREADS 768
#define NCH   8
// per-stage smem: A 16KB @0, W 24KB @16384, S 16KB @40960
#define OFF_W 16384
#define OFF_S 40960
#define BUFB  57344
#define SMEM_BYTES (3 * BUFB)   // 172032; epilogue zs 128*193*4=98816 reuses

// pre-tiled, pre-swizzled fp16 staging (device globals)
// g_xh2: [mt128 512][ch 8][r 128][64h swz]   (ch = K/64 of [x|h])
// g_s2 : [mt128 512][ch 4][r 128][64h swz]
// g_w2 : [jt 8][ch 8][r 192][64h swz]        (r = gate*32+j)
__device__ uint4 g_xh2[(size_t)B_TOT * 512 / 8];
__device__ uint4 g_s2 [(size_t)B_TOT * 256 / 8];
__device__ uint4 g_w2 [3072 * 256 / 8];

// ---------------- helpers ----------------
__device__ __forceinline__ unsigned sm_u32(const void* p) {
    return (unsigned)__cvta_generic_to_shared(const_cast<void*>(p));
}
__device__ __forceinline__ void bulkN(void* dst, const void* src, unsigned bytes, unsigned mb) {
    asm volatile("cp.async.bulk.shared::cta.global.mbarrier::complete_tx::bytes "
                 "[%0], [%1], %2, [%3];"
                 :: "r"(sm_u32(dst)), "l"(src), "r"(bytes), "r"(mb) : "memory");
}
__device__ __forceinline__ void ldsm4(unsigned r[4], const void* p) {
    unsigned addr = sm_u32(p);
    asm volatile("ldmatrix.sync.aligned.m8n8.x4.shared.b16 {%0,%1,%2,%3}, [%4];"
                 : "=r"(r[0]), "=r"(r[1]), "=r"(r[2]), "=r"(r[3]) : "r"(addr));
}
__device__ __forceinline__ void mma16816(float c[4], const unsigned a[4],
                                         unsigned b0, unsigned b1) {
    asm volatile(
        "mma.sync.aligned.m16n8k16.row.col.f32.f16.f16.f32 "
        "{%0,%1,%2,%3}, {%4,%5,%6,%7}, {%8,%9}, {%0,%1,%2,%3};"
        : "+f"(c[0]), "+f"(c[1]), "+f"(c[2]), "+f"(c[3])
        : "r"(a[0]), "r"(a[1]), "r"(a[2]), "r"(a[3]), "r"(b0), "r"(b1));
}
__device__ __forceinline__ void mbar_wait(unsigned addr, int parity) {
    asm volatile("{\n\t.reg .pred P;\n"
                 "WL%=:\n\t"
                 "mbarrier.try_wait.parity.acquire.cta.shared::cta.b64 P, [%0], %1, 0x989680;\n\t"
                 "@P bra.uni WD%=;\n\t"
                 "bra.uni WL%=;\n"
                 "WD%=:\n\t}"
                 :: "r"(addr), "r"(parity) : "memory");
}
__device__ __forceinline__ float sigmoidf_(float x) {
    return 1.0f / (1.0f + expf(-x));
}
__device__ __forceinline__ uint4 pack8(const float4 a, const float4 b) {
    __half2 h0 = __floats2half2_rn(a.x, a.y), h1 = __floats2half2_rn(a.z, a.w);
    __half2 h2 = __floats2half2_rn(b.x, b.y), h3 = __floats2half2_rn(b.z, b.w);
    uint4 u;
    u.x = *(unsigned*)&h0; u.y = *(unsigned*)&h1;
    u.z = *(unsigned*)&h2; u.w = *(unsigned*)&h3;
    return u;
}

// ---------------- conversion kernels (tile + swizzle) ----------------
__global__ void cvt_xh_kernel(const float* __restrict__ x, const float* __restrict__ h) {
    const int N = B_TOT * 64;
    for (int t = blockIdx.x * blockDim.x + threadIdx.x; t < N; t += gridDim.x * blockDim.x) {
        const int m = t >> 6, gk = t & 63;
        const int c = gk >> 3, gi = gk & 7;
        const int mt = m >> 7, r = m & 127;
        const int gis = gi ^ (r & 7);
        const float4* src = (gk < 32)
            ? (const float4*)x + (size_t)m * 64 + gk * 2
            : (const float4*)h + (size_t)m * 64 + (gk - 32) * 2;
        g_xh2[(((size_t)(mt * 8 + c) * 128 + r) * 8) + gis] = pack8(src[0], src[1]);
    }
}
__global__ void cvt_s_kernel(const float* __restrict__ s, const int* __restrict__ pidx) {
    const int N = B_TOT * 32;
    const float4* src0 = (const float4*)(s + (size_t)(*pidx) * B_TOT * DH);
    for (int t = blockIdx.x * blockDim.x + threadIdx.x; t < N; t += gridDim.x * blockDim.x) {
        const int m = t >> 5, gk = t & 31;
        const int c = gk >> 3, gi = gk & 7;
        const int mt = m >> 7, r = m & 127;
        const int gis = gi ^ (r & 7);
        const float4* src = src0 + (size_t)m * 64 + gk * 2;
        g_s2[(((size_t)(mt * 4 + c) * 128 + r) * 8) + gis] = pack8(src[0], src[1]);
    }
}
__global__ void cvt_w_kernel(const float* __restrict__ wih, const float* __restrict__ whh,
                             const float* __restrict__ wsh) {
    const int N = 64 * 192 * 8;
    for (int t = blockIdx.x * blockDim.x + threadIdx.x; t < N; t += gridDim.x * blockDim.x) {
        const int gi = t & 7;
        const int r  = (t >> 3) % 192;
        const int bc = (t >> 3) / 192;        // jt*8 + c
        const int jt = bc >> 3, c = bc & 7;
        const int g = r >> 5, j = r & 31;
        const int jj = jt * 32 + j;
        const int kq = (c < 4 ? c * 64 : (c - 4) * 64) + gi * 8;
        const float4* src;
        if (c < 4)      src = (const float4*)wih + ((size_t)(g * 256 + jj) * 256 + kq) / 4;
        else if (g < 4) src = (const float4*)whh + ((size_t)(g * 256 + jj) * 256 + kq) / 4;
        else            src = (const float4*)wsh + ((size_t)((g - 4) * 256 + jj) * 256 + kq) / 4;
        const int gis = gi ^ (r & 7);
        g_w2[((size_t)bc * 192 + r) * 8 + gis] = pack8(src[0], src[1]);
    }
}

// ---------------- GEMM + fused epilogue ----------------
__global__ __launch_bounds__(THREADS, 1)
void lstm_gemm_kernel(const float* __restrict__ cm,
                      const float* __restrict__ mask,
                      const float* __restrict__ bih,
                      const float* __restrict__ bhh,
                      const float* __restrict__ bsh,
                      float* __restrict__ out)
{
    extern __shared__ char smem[];
    __shared__ float sBias[192];
    __shared__ __align__(8) unsigned long long sMbar[3];

    const int tid  = threadIdx.x;
    const int lane = tid & 31;
    const int wid  = tid >> 5;
    const int warp_m = wid & 3;      // 4 m-warps * 32 rows = 128
    const int warp_n = wid >> 2;     // 6 n-warps * 32 cols (warp_n == gate)
    const int jt = blockIdx.x;
    const int mt = blockIdx.y;       // 128-row tiles (512)
    const int j0 = jt * 32;
    const int m0 = mt * BM;

    if (tid < 192) {
        const int g = tid >> 5, j = tid & 31, jj = j0 + j;
        float b = bih[g * DH + jj];
        b += (g < 4) ? bhh[g * DH + jj] : bsh[(g - 4) * DH + jj];
        sBias[tid] = b;
    }
    if (tid == 0) {
        #pragma unroll
        for (int i = 0; i < 3; ++i)
            asm volatile("mbarrier.init.shared.b64 [%0], 1;"
                         :: "r"(sm_u32(&sMbar[i])) : "memory");
        asm volatile("fence.proxy.async.shared::cta;" ::: "memory");
    }
    __syncthreads();

    const unsigned mbA[3] = { sm_u32(&sMbar[0]), sm_u32(&sMbar[1]), sm_u32(&sMbar[2]) };

    float acc[2][4][4];
    #pragma unroll
    for (int a = 0; a < 2; ++a)
        #pragma unroll
        for (int b = 0; b < 4; ++b)
            #pragma unroll
            for (int d = 0; d < 4; ++d) acc[a][b][d] = 0.0f;

    // ---- stage one K-chunk: 2-3 bulk copies (pre-tiled, pre-swizzled) ----
    auto stage = [&](int ch) {
        if (tid != 0) return;
        char* buf = smem + (ch % 3) * BUFB;
        const unsigned mb = mbA[ch % 3];
        const unsigned bytes = (ch >= 4) ? 57344u : 40960u;
        asm volatile("mbarrier.arrive.expect_tx.shared.b64 _, [%0], %1;"
                     :: "r"(mb), "r"(bytes) : "memory");
        bulkN(buf,         g_xh2 + (size_t)(mt * 8 + ch) * 1024, 16384u, mb);
        bulkN(buf + OFF_W, g_w2  + (size_t)(jt * 8 + ch) * 1536, 24576u, mb);
        if (ch >= 4)
            bulkN(buf + OFF_S, g_s2 + (size_t)(mt * 4 + (ch - 4)) * 1024, 16384u, mb);
    };

    // ---- mma over one K chunk (4 x k16), warp tile 32m x 32n ----
    const int arow = lane & 15;
    const int ak8  = (lane >> 4) & 1;
    const int brow8 = ((lane >> 4) << 3) + (lane & 7);
    const int bk8  = (lane >> 3) & 1;

    auto mma_chunk = [&](int ch) {
        const char* buf = smem + (ch % 3) * BUFB;
        const char* A = buf + ((ch >= 4 && warp_n >= 4) ? OFF_S : 0);
        const char* W = buf + OFF_W;
        #pragma unroll
        for (int kq = 0; kq < 4; ++kq) {
            unsigned a0[4], a1[4];
            {
                const int r0 = warp_m * 32 + arow;
                const int r1 = r0 + 16;
                const int g = kq * 2 + ak8;
                ldsm4(a0, A + r0 * 128 + ((g ^ (r0 & 7)) << 4));
                ldsm4(a1, A + r1 * 128 + ((g ^ (r1 & 7)) << 4));
            }
            unsigned bb[2][4];
            #pragma unroll
            for (int nf2 = 0; nf2 < 2; ++nf2) {
                const int r = warp_n * 32 + nf2 * 16 + brow8;
                const int g = kq * 2 + bk8;
                ldsm4(bb[nf2], W + r * 128 + ((g ^ (r & 7)) << 4));
            }
            #pragma unroll
            for (int nf2 = 0; nf2 < 2; ++nf2) {
                mma16816(acc[0][nf2 * 2    ], a0, bb[nf2][0], bb[nf2][1]);
                mma16816(acc[0][nf2 * 2 + 1], a0, bb[nf2][2], bb[nf2][3]);
                mma16816(acc[1][nf2 * 2    ], a1, bb[nf2][0], bb[nf2][1]);
                mma16816(acc[1][nf2 * 2 + 1], a1, bb[nf2][2], bb[nf2][3]);
            }
        }
    };

    // ---- 3-stage pipelined mainloop ----
    stage(0);
    stage(1);
    int ph0 = 0, ph1 = 0, ph2 = 0;
    #pragma unroll
    for (int ch = 0; ch < NCH; ++ch) {
        const int b = ch % 3;
        if (b == 0)      { mbar_wait(mbA[0], ph0); ph0 ^= 1; }
        else if (b == 1) { mbar_wait(mbA[1], ph1); ph1 ^= 1; }
        else             { mbar_wait(mbA[2], ph2); ph2 ^= 1; }
        __syncthreads();                 // readers of chunk ch-1 done -> its buf reusable
        if (ch + 2 < NCH) stage(ch + 2); // writes buf (ch+2)%3 == (ch-1)%3
        mma_chunk(ch);
    }
    __syncthreads();

    // ---- epilogue: accums -> smem so each thread sees all 6 gates ----
    float* zs = (float*)smem;   // [128][193]
    const int q  = lane >> 2;
    const int cq = lane & 3;
    #pragma unroll
    for (int mf = 0; mf < 2; ++mf)
        #pragma unroll
        for (int nf = 0; nf < 4; ++nf) {
            const int row = warp_m * 32 + mf * 16 + q;
            const int col = warp_n * 32 + nf * 8 + 2 * cq;
            zs[(row    ) * 193 + col    ] = acc[mf][nf][0];
            zs[(row    ) * 193 + col + 1] = acc[mf][nf][1];
            zs[(row + 8) * 193 + col    ] = acc[mf][nf][2];
            zs[(row + 8) * 193 + col + 1] = acc[mf][nf][3];
        }
    __syncthreads();

    const size_t PLANE = (size_t)B_TOT * DH;
    for (int e = tid; e < BM * 32; e += THREADS) {
        const int m = e >> 5;
        const int j = e & 31;
        const int n = m0 + m;
        const int jj = j0 + j;
        const float* zrow = zs + (size_t)m * 193;
        const float zi  = zrow[      j] + sBias[      j];
        const float zf  = zrow[ 32 + j] + sBias[ 32 + j];
        const float zo  = zrow[ 64 + j] + sBias[ 64 + j];
        const float zc  = zrow[ 96 + j] + sBias[ 96 + j];
        const float zb0 = zrow[128 + j] + sBias[128 + j];
        const float zb1 = zrow[160 + j] + sBias[160 + j];

        const float ig  = sigmoidf_(zi);
        const float fg  = sigmoidf_(zf);
        const float og  = sigmoidf_(zo);
        const float bg0 = sigmoidf_(zb0);
        const float bg1 = sigmoidf_(zb1);

        const float mval = mask[n];
        const float cold = cm[(size_t)n * DH + jj];
        const float ct = (fg * cold + ig * tanhf(zc)) * mval;
        const float tc = tanhf(ct) * mval;

        const size_t base = (size_t)n * DH + jj;
        out[base            ] = og  * tc;
        out[PLANE     + base] = ct;
        out[2 * PLANE + base] = bg0 * tc;
        out[3 * PLANE + base] = bg1 * tc;
    }
}

extern "C" void kernel_launch(void* const* d_in, const int* in_sizes, int n_in,
                              void* d_out, int out_size) {
    (void)in_sizes; (void)n_in; (void)out_size;
    const float* x    = (const float*)d_in[0];
    const float* hm   = (const float*)d_in[1];
    const float* cm   = (const float*)d_in[2];
    const float* sm   = (const float*)d_in[3];
    const float* mask = (const float*)d_in[4];
    const float* wih  = (const float*)d_in[5];
    const float* whh  = (const float*)d_in[6];
    const float* wsh  = (const float*)d_in[7];
    const float* bih  = (const float*)d_in[8];
    const float* bhh  = (const float*)d_in[9];
    const float* bsh  = (const float*)d_in[10];
    const int*   idx  = (const int*)d_in[11];
    float* out = (float*)d_out;

    cvt_xh_kernel<<<2048, 256>>>(x, hm);
    cvt_s_kernel<<<2048, 256>>>(sm, idx);
    cvt_w_kernel<<<384, 256>>>(wih, whh, wsh);

    cudaFuncSetAttribute(lstm_gemm_kernel,
                         cudaFuncAttributeMaxDynamicSharedMemorySize, SMEM_BYTES);
    dim3 grid(DH / 32, B_TOT / BM);   // (8, 512): j fast -> activation reuse in L2
    lstm_gemm_kernel<<<grid, THREADS, SMEM_BYTES>>>(cm, mask, bih, bhh, bsh, out);
}

// round 16
// speedup vs baseline: 1.6538x; 1.6538x over previous
#include <cuda_runtime.h>
#include <cuda_fp16.h>
#include <math.h>
#include <stdint.h>

#define B_TOT 65536
#define DH    256
#define BM    64
#define THREADS 384
#define NCH   8
// smem: 3-deep A+W ring (stage = A 8KB @0, W 24KB @8192), 2-deep S ring @98304
#define AW_STRIDE 32768
#define OFF_W 8192
#define OFF_S 98304
#define SMEM_BYTES 114688   // 98304 + 2*8192; epilogue zs 64*193*4=49408 reuses

// pre-tiled, pre-swizzled fp16 staging (device globals)
// g_xh2: [mt128 512][ch 8][r 128][64h swz]   (ch = K/64 of [x|h])
// g_s2 : [mt128 512][ch 4][r 128][64h swz]
// g_w2 : [jt 8][ch 8][r 192][64h swz]        (r = gate*32+j)
__device__ uint4 g_xh2[(size_t)B_TOT * 512 / 8];
__device__ uint4 g_s2 [(size_t)B_TOT * 256 / 8];
__device__ uint4 g_w2 [3072 * 256 / 8];

// ---------------- helpers ----------------
__device__ __forceinline__ unsigned sm_u32(const void* p) {
    return (unsigned)__cvta_generic_to_shared(const_cast<void*>(p));
}
__device__ __forceinline__ void bulkN(void* dst, const void* src, unsigned bytes, unsigned mb) {
    asm volatile("cp.async.bulk.shared::cta.global.mbarrier::complete_tx::bytes "
                 "[%0], [%1], %2, [%3];"
                 :: "r"(sm_u32(dst)), "l"(src), "r"(bytes), "r"(mb) : "memory");
}
__device__ __forceinline__ void ldsm4(unsigned r[4], const void* p) {
    unsigned addr = sm_u32(p);
    asm volatile("ldmatrix.sync.aligned.m8n8.x4.shared.b16 {%0,%1,%2,%3}, [%4];"
                 : "=r"(r[0]), "=r"(r[1]), "=r"(r[2]), "=r"(r[3]) : "r"(addr));
}
__device__ __forceinline__ void mma16816(float c[4], const unsigned a[4],
                                         unsigned b0, unsigned b1) {
    asm volatile(
        "mma.sync.aligned.m16n8k16.row.col.f32.f16.f16.f32 "
        "{%0,%1,%2,%3}, {%4,%5,%6,%7}, {%8,%9}, {%0,%1,%2,%3};"
        : "+f"(c[0]), "+f"(c[1]), "+f"(c[2]), "+f"(c[3])
        : "r"(a[0]), "r"(a[1]), "r"(a[2]), "r"(a[3]), "r"(b0), "r"(b1));
}
__device__ __forceinline__ void mbar_wait(unsigned addr, int parity) {
    asm volatile("{\n\t.reg .pred P;\n"
                 "WL%=:\n\t"
                 "mbarrier.try_wait.parity.acquire.cta.shared::cta.b64 P, [%0], %1, 0x989680;\n\t"
                 "@P bra.uni WD%=;\n\t"
                 "bra.uni WL%=;\n"
                 "WD%=:\n\t}"
                 :: "r"(addr), "r"(parity) : "memory");
}
__device__ __forceinline__ float sigmoidf_(float x) {
    return 1.0f / (1.0f + expf(-x));
}
__device__ __forceinline__ uint4 pack8(const float4 a, const float4 b) {
    __half2 h0 = __floats2half2_rn(a.x, a.y), h1 = __floats2half2_rn(a.z, a.w);
    __half2 h2 = __floats2half2_rn(b.x, b.y), h3 = __floats2half2_rn(b.z, b.w);
    uint4 u;
    u.x = *(unsigned*)&h0; u.y = *(unsigned*)&h1;
    u.z = *(unsigned*)&h2; u.w = *(unsigned*)&h3;
    return u;
}

// ---------------- conversion kernels (tile + swizzle) ----------------
__global__ void cvt_xh_kernel(const float* __restrict__ x, const float* __restrict__ h) {
    const int N = B_TOT * 64;
    for (int t = blockIdx.x * blockDim.x + threadIdx.x; t < N; t += gridDim.x * blockDim.x) {
        const int m = t >> 6, gk = t & 63;
        const int c = gk >> 3, gi = gk & 7;
        const int mt = m >> 7, r = m & 127;
        const int gis = gi ^ (r & 7);
        const float4* src = (gk < 32)
            ? (const float4*)x + (size_t)m * 64 + gk * 2
            : (const float4*)h + (size_t)m * 64 + (gk - 32) * 2;
        g_xh2[(((size_t)(mt * 8 + c) * 128 + r) * 8) + gis] = pack8(src[0], src[1]);
    }
}
__global__ void cvt_s_kernel(const float* __restrict__ s, const int* __restrict__ pidx) {
    const int N = B_TOT * 32;
    const float4* src0 = (const float4*)(s + (size_t)(*pidx) * B_TOT * DH);
    for (int t = blockIdx.x * blockDim.x + threadIdx.x; t < N; t += gridDim.x * blockDim.x) {
        const int m = t >> 5, gk = t & 31;
        const int c = gk >> 3, gi = gk & 7;
        const int mt = m >> 7, r = m & 127;
        const int gis = gi ^ (r & 7);
        const float4* src = src0 + (size_t)m * 64 + gk * 2;
        g_s2[(((size_t)(mt * 4 + c) * 128 + r) * 8) + gis] = pack8(src[0], src[1]);
    }
}
__global__ void cvt_w_kernel(const float* __restrict__ wih, const float* __restrict__ whh,
                             const float* __restrict__ wsh) {
    const int N = 64 * 192 * 8;
    for (int t = blockIdx.x * blockDim.x + threadIdx.x; t < N; t += gridDim.x * blockDim.x) {
        const int gi = t & 7;
        const int r  = (t >> 3) % 192;
        const int bc = (t >> 3) / 192;        // jt*8 + c
        const int jt = bc >> 3, c = bc & 7;
        const int g = r >> 5, j = r & 31;
        const int jj = jt * 32 + j;
        const int kq = (c < 4 ? c * 64 : (c - 4) * 64) + gi * 8;
        const float4* src;
        if (c < 4)      src = (const float4*)wih + ((size_t)(g * 256 + jj) * 256 + kq) / 4;
        else if (g < 4) src = (const float4*)whh + ((size_t)(g * 256 + jj) * 256 + kq) / 4;
        else            src = (const float4*)wsh + ((size_t)((g - 4) * 256 + jj) * 256 + kq) / 4;
        const int gis = gi ^ (r & 7);
        g_w2[((size_t)bc * 192 + r) * 8 + gis] = pack8(src[0], src[1]);
    }
}

// ---------------- GEMM + fused epilogue ----------------
__global__ __launch_bounds__(THREADS, 2)
void lstm_gemm_kernel(const float* __restrict__ cm,
                      const float* __restrict__ mask,
                      const float* __restrict__ bih,
                      const float* __restrict__ bhh,
                      const float* __restrict__ bsh,
                      float* __restrict__ out)
{
    extern __shared__ char smem[];
    __shared__ float sBias[192];
    __shared__ __align__(8) unsigned long long sMbarAW[3];
    __shared__ __align__(8) unsigned long long sMbarS[2];

    const int tid  = threadIdx.x;
    const int lane = tid & 31;
    const int wid  = tid >> 5;
    const int warp_m = wid & 1;      // 2 m-warps * 32 rows
    const int warp_n = wid >> 1;     // 6 n-warps * 32 cols (warp_n == gate)
    const int jt = blockIdx.x;
    const int mt = blockIdx.y;       // 64-row tiles (1024)
    const int j0 = jt * 32;
    const int m0 = mt * BM;
    const int mt128 = mt >> 1;
    const int half  = mt & 1;        // which 64-row half of the 128-row gmem tile

    if (tid < 192) {
        const int g = tid >> 5, j = tid & 31, jj = j0 + j;
        float b = bih[g * DH + jj];
        b += (g < 4) ? bhh[g * DH + jj] : bsh[(g - 4) * DH + jj];
        sBias[tid] = b;
    }
    if (tid == 0) {
        #pragma unroll
        for (int i = 0; i < 3; ++i)
            asm volatile("mbarrier.init.shared.b64 [%0], 1;"
                         :: "r"(sm_u32(&sMbarAW[i])) : "memory");
        #pragma unroll
        for (int i = 0; i < 2; ++i)
            asm volatile("mbarrier.init.shared.b64 [%0], 1;"
                         :: "r"(sm_u32(&sMbarS[i])) : "memory");
        asm volatile("fence.proxy.async.shared::cta;" ::: "memory");
    }
    __syncthreads();

    const unsigned mbAW[3] = { sm_u32(&sMbarAW[0]), sm_u32(&sMbarAW[1]), sm_u32(&sMbarAW[2]) };
    const unsigned mbS[2]  = { sm_u32(&sMbarS[0]), sm_u32(&sMbarS[1]) };

    float acc[2][4][4];
    #pragma unroll
    for (int a = 0; a < 2; ++a)
        #pragma unroll
        for (int b = 0; b < 4; ++b)
            #pragma unroll
            for (int d = 0; d < 4; ++d) acc[a][b][d] = 0.0f;

    // ---- stage A+W for one chunk (lookahead 2, 3-deep ring) ----
    auto stage_aw = [&](int ch) {
        if (tid != 0) return;
        char* buf = smem + (ch % 3) * AW_STRIDE;
        const unsigned mb = mbAW[ch % 3];
        asm volatile("mbarrier.arrive.expect_tx.shared.b64 _, [%0], %1;"
                     :: "r"(mb), "r"(32768u) : "memory");
        bulkN(buf,         g_xh2 + (size_t)(mt128 * 8 + ch) * 1024 + half * 512, 8192u, mb);
        bulkN(buf + OFF_W, g_w2  + (size_t)(jt * 8 + ch) * 1536, 24576u, mb);
    };
    // ---- stage S for chunk sch+4 (lookahead 1, 2-deep ring) ----
    auto stage_s = [&](int sch) {
        if (tid != 0) return;
        char* buf = smem + OFF_S + (sch & 1) * 8192;
        const unsigned mb = mbS[sch & 1];
        asm volatile("mbarrier.arrive.expect_tx.shared.b64 _, [%0], %1;"
                     :: "r"(mb), "r"(8192u) : "memory");
        bulkN(buf, g_s2 + (size_t)(mt128 * 4 + sch) * 1024 + half * 512, 8192u, mb);
    };

    // ---- mma over one K chunk (4 x k16), warp tile 32m x 32n ----
    const int arow = lane & 15;
    const int ak8  = (lane >> 4) & 1;
    const int brow8 = ((lane >> 4) << 3) + (lane & 7);
    const int bk8  = (lane >> 3) & 1;

    auto mma_chunk = [&](int ch) {
        const char* aw = smem + (ch % 3) * AW_STRIDE;
        const char* A = (ch >= 4 && warp_n >= 4)
                      ? smem + OFF_S + ((ch - 4) & 1) * 8192
                      : aw;
        const char* W = aw + OFF_W;
        #pragma unroll
        for (int kq = 0; kq < 4; ++kq) {
            unsigned a0[4], a1[4];
            {
                const int r0 = warp_m * 32 + arow;
                const int r1 = r0 + 16;
                const int g = kq * 2 + ak8;
                ldsm4(a0, A + r0 * 128 + ((g ^ (r0 & 7)) << 4));
                ldsm4(a1, A + r1 * 128 + ((g ^ (r1 & 7)) << 4));
            }
            unsigned bb[2][4];
            #pragma unroll
            for (int nf2 = 0; nf2 < 2; ++nf2) {
                const int r = warp_n * 32 + nf2 * 16 + brow8;
                const int g = kq * 2 + bk8;
                ldsm4(bb[nf2], W + r * 128 + ((g ^ (r & 7)) << 4));
            }
            #pragma unroll
            for (int nf2 = 0; nf2 < 2; ++nf2) {
                mma16816(acc[0][nf2 * 2    ], a0, bb[nf2][0], bb[nf2][1]);
                mma16816(acc[0][nf2 * 2 + 1], a0, bb[nf2][2], bb[nf2][3]);
                mma16816(acc[1][nf2 * 2    ], a1, bb[nf2][0], bb[nf2][1]);
                mma16816(acc[1][nf2 * 2 + 1], a1, bb[nf2][2], bb[nf2][3]);
            }
        }
    };

    // ---- pipelined mainloop: AW lookahead-2, S lookahead-1 ----
    stage_aw(0);
    stage_aw(1);
    int phAW0 = 0, phAW1 = 0, phAW2 = 0;
    int phS0 = 0, phS1 = 0;
    #pragma unroll
    for (int ch = 0; ch < NCH; ++ch) {
        const int b = ch % 3;
        if (b == 0)      { mbar_wait(mbAW[0], phAW0); phAW0 ^= 1; }
        else if (b == 1) { mbar_wait(mbAW[1], phAW1); phAW1 ^= 1; }
        else             { mbar_wait(mbAW[2], phAW2); phAW2 ^= 1; }
        if (ch >= 4) {
            if ((ch - 4) & 1) { mbar_wait(mbS[1], phS1); phS1 ^= 1; }
            else              { mbar_wait(mbS[0], phS0); phS0 ^= 1; }
        }
        __syncthreads();   // readers of chunk ch-1 done -> AW slot (ch+2)%3 & S slot reusable
        if (ch + 2 < NCH) stage_aw(ch + 2);
        if (ch + 1 >= 4 && ch + 1 < NCH) stage_s(ch + 1 - 4);
        mma_chunk(ch);
    }
    __syncthreads();

    // ---- epilogue: accums -> smem so each thread sees all 6 gates ----
    float* zs = (float*)smem;   // [64][193]
    const int q  = lane >> 2;
    const int cq = lane & 3;
    #pragma unroll
    for (int mf = 0; mf < 2; ++mf)
        #pragma unroll
        for (int nf = 0; nf < 4; ++nf) {
            const int row = warp_m * 32 + mf * 16 + q;
            const int col = warp_n * 32 + nf * 8 + 2 * cq;
            zs[(row    ) * 193 + col    ] = acc[mf][nf][0];
            zs[(row    ) * 193 + col + 1] = acc[mf][nf][1];
            zs[(row + 8) * 193 + col    ] = acc[mf][nf][2];
            zs[(row + 8) * 193 + col + 1] = acc[mf][nf][3];
        }
    __syncthreads();

    const size_t PLANE = (size_t)B_TOT * DH;
    for (int e = tid; e < BM * 32; e += THREADS) {
        const int m = e >> 5;
        const int j = e & 31;
        const int n = m0 + m;
        const int jj = j0 + j;
        const float* zrow = zs + (size_t)m * 193;
        const float zi  = zrow[      j] + sBias[      j];
        const float zf  = zrow[ 32 + j] + sBias[ 32 + j];
        const float zo  = zrow[ 64 + j] + sBias[ 64 + j];
        const float zc  = zrow[ 96 + j] + sBias[ 96 + j];
        const float zb0 = zrow[128 + j] + sBias[128 + j];
        const float zb1 = zrow[160 + j] + sBias[160 + j];

        const float ig  = sigmoidf_(zi);
        const float fg  = sigmoidf_(zf);
        const float og  = sigmoidf_(zo);
        const float bg0 = sigmoidf_(zb0);
        const float bg1 = sigmoidf_(zb1);

        const float mval = mask[n];
        const float cold = cm[(size_t)n * DH + jj];
        const float ct = (fg * cold + ig * tanhf(zc)) * mval;
        const float tc = tanhf(ct) * mval;

        const size_t base = (size_t)n * DH + jj;
        out[base            ] = og  * tc;
        out[PLANE     + base] = ct;
        out[2 * PLANE + base] = bg0 * tc;
        out[3 * PLANE + base] = bg1 * tc;
    }
}

extern "C" void kernel_launch(void* const* d_in, const int* in_sizes, int n_in,
                              void* d_out, int out_size) {
    (void)in_sizes; (void)n_in; (void)out_size;
    const float* x    = (const float*)d_in[0];
    const float* hm   = (const float*)d_in[1];
    const float* cm   = (const float*)d_in[2];
    const float* sm   = (const float*)d_in[3];
    const float* mask = (const float*)d_in[4];
    const float* wih  = (const float*)d_in[5];
    const float* whh  = (const float*)d_in[6];
    const float* wsh  = (const float*)d_in[7];
    const float* bih  = (const float*)d_in[8];
    const float* bhh  = (const float*)d_in[9];
    const float* bsh  = (const float*)d_in[10];
    const int*   idx  = (const int*)d_in[11];
    float* out = (float*)d_out;

    cvt_xh_kernel<<<2048, 256>>>(x, hm);
    cvt_s_kernel<<<2048, 256>>>(sm, idx);
    cvt_w_kernel<<<384, 256>>>(wih, whh, wsh);

    cudaFuncSetAttribute(lstm_gemm_kernel,
                         cudaFuncAttributeMaxDynamicSharedMemorySize, SMEM_BYTES);
    dim3 grid(DH / 32, B_TOT / BM);   // (8, 1024): j fast -> activation reuse in L2
    lstm_gemm_kernel<<<grid, THREADS, SMEM_BYTES>>>(cm, mask, bih, bhh, bsh, out);
}

// round 17
// speedup vs baseline: 1.6870x; 1.0201x over previous
#include <cuda_runtime.h>
#include <cuda_fp16.h>
#include <math.h>
#include <stdint.h>

#define B_TOT 65536
#define DH    256
#define BM    64
#define THREADS 384
#define NCH   8
// smem: 3-deep A+W ring (stage = A 8KB @0, W 24KB @8192), 2-deep S ring @98304
#define AW_STRIDE 32768
#define OFF_W 8192
#define OFF_S 98304
#define SMEM_BYTES 114688   // 98304 + 2*8192; epilogue zs 64*193*4=49408 reuses

// pre-tiled, pre-swizzled fp16 staging (device globals)
// g_xh2: [mt128 512][ch 8][r 128][64h swz]   (ch = K/64 of [x|h])
// g_s2 : [mt128 512][ch 4][r 128][64h swz]
// g_w2 : [jt 8][ch 8][r 192][64h swz]        (r = gate*32+j)
__device__ uint4 g_xh2[(size_t)B_TOT * 512 / 8];
__device__ uint4 g_s2 [(size_t)B_TOT * 256 / 8];
__device__ uint4 g_w2 [3072 * 256 / 8];

// ---------------- helpers ----------------
__device__ __forceinline__ unsigned sm_u32(const void* p) {
    return (unsigned)__cvta_generic_to_shared(const_cast<void*>(p));
}
__device__ __forceinline__ void bulkN(void* dst, const void* src, unsigned bytes, unsigned mb) {
    asm volatile("cp.async.bulk.shared::cta.global.mbarrier::complete_tx::bytes "
                 "[%0], [%1], %2, [%3];"
                 :: "r"(sm_u32(dst)), "l"(src), "r"(bytes), "r"(mb) : "memory");
}
__device__ __forceinline__ void ldsm4(unsigned r[4], const void* p) {
    unsigned addr = sm_u32(p);
    asm volatile("ldmatrix.sync.aligned.m8n8.x4.shared.b16 {%0,%1,%2,%3}, [%4];"
                 : "=r"(r[0]), "=r"(r[1]), "=r"(r[2]), "=r"(r[3]) : "r"(addr));
}
__device__ __forceinline__ void mma16816(float c[4], const unsigned a[4],
                                         unsigned b0, unsigned b1) {
    asm volatile(
        "mma.sync.aligned.m16n8k16.row.col.f32.f16.f16.f32 "
        "{%0,%1,%2,%3}, {%4,%5,%6,%7}, {%8,%9}, {%0,%1,%2,%3};"
        : "+f"(c[0]), "+f"(c[1]), "+f"(c[2]), "+f"(c[3])
        : "r"(a[0]), "r"(a[1]), "r"(a[2]), "r"(a[3]), "r"(b0), "r"(b1));
}
__device__ __forceinline__ void mbar_wait(unsigned addr, int parity) {
    asm volatile("{\n\t.reg .pred P;\n"
                 "WL%=:\n\t"
                 "mbarrier.try_wait.parity.acquire.cta.shared::cta.b64 P, [%0], %1, 0x989680;\n\t"
                 "@P bra.uni WD%=;\n\t"
                 "bra.uni WL%=;\n"
                 "WD%=:\n\t}"
                 :: "r"(addr), "r"(parity) : "memory");
}
__device__ __forceinline__ void mbar_arrive(unsigned addr) {
    asm volatile("mbarrier.arrive.release.cta.shared::cta.b64 _, [%0];"
                 :: "r"(addr) : "memory");
}
__device__ __forceinline__ float sigmoidf_(float x) {
    return 1.0f / (1.0f + expf(-x));
}
__device__ __forceinline__ uint4 pack8(const float4 a, const float4 b) {
    __half2 h0 = __floats2half2_rn(a.x, a.y), h1 = __floats2half2_rn(a.z, a.w);
    __half2 h2 = __floats2half2_rn(b.x, b.y), h3 = __floats2half2_rn(b.z, b.w);
    uint4 u;
    u.x = *(unsigned*)&h0; u.y = *(unsigned*)&h1;
    u.z = *(unsigned*)&h2; u.w = *(unsigned*)&h3;
    return u;
}

// ---------------- fused conversion kernel (tile + swizzle) ----------------
#define N_XH (B_TOT * 64)
#define N_S  (B_TOT * 32)
#define N_W  (64 * 192 * 8)
__global__ void cvt_all_kernel(const float* __restrict__ x, const float* __restrict__ h,
                               const float* __restrict__ s, const int* __restrict__ pidx,
                               const float* __restrict__ wih, const float* __restrict__ whh,
                               const float* __restrict__ wsh) {
    const float4* s0 = (const float4*)(s + (size_t)(*pidx) * B_TOT * DH);
    const int NT = N_XH + N_S + N_W;
    for (int t = blockIdx.x * blockDim.x + threadIdx.x; t < NT; t += gridDim.x * blockDim.x) {
        if (t < N_XH) {
            const int m = t >> 6, gk = t & 63;
            const int c = gk >> 3, gi = gk & 7;
            const int mt = m >> 7, r = m & 127;
            const int gis = gi ^ (r & 7);
            const float4* src = (gk < 32)
                ? (const float4*)x + (size_t)m * 64 + gk * 2
                : (const float4*)h + (size_t)m * 64 + (gk - 32) * 2;
            g_xh2[(((size_t)(mt * 8 + c) * 128 + r) * 8) + gis] = pack8(src[0], src[1]);
        } else if (t < N_XH + N_S) {
            const int ts = t - N_XH;
            const int m = ts >> 5, gk = ts & 31;
            const int c = gk >> 3, gi = gk & 7;
            const int mt = m >> 7, r = m & 127;
            const int gis = gi ^ (r & 7);
            const float4* src = s0 + (size_t)m * 64 + gk * 2;
            g_s2[(((size_t)(mt * 4 + c) * 128 + r) * 8) + gis] = pack8(src[0], src[1]);
        } else {
            const int tw = t - N_XH - N_S;
            const int gi = tw & 7;
            const int r  = (tw >> 3) % 192;
            const int bc = (tw >> 3) / 192;        // jt*8 + c
            const int jt = bc >> 3, c = bc & 7;
            const int g = r >> 5, j = r & 31;
            const int jj = jt * 32 + j;
            const int kq = (c < 4 ? c * 64 : (c - 4) * 64) + gi * 8;
            const float4* src;
            if (c < 4)      src = (const float4*)wih + ((size_t)(g * 256 + jj) * 256 + kq) / 4;
            else if (g < 4) src = (const float4*)whh + ((size_t)(g * 256 + jj) * 256 + kq) / 4;
            else            src = (const float4*)wsh + ((size_t)((g - 4) * 256 + jj) * 256 + kq) / 4;
            const int gis = gi ^ (r & 7);
            g_w2[((size_t)bc * 192 + r) * 8 + gis] = pack8(src[0], src[1]);
        }
    }
}

// ---------------- GEMM + fused epilogue ----------------
__global__ __launch_bounds__(THREADS, 2)
void lstm_gemm_kernel(const float* __restrict__ cm,
                      const float* __restrict__ mask,
                      const float* __restrict__ bih,
                      const float* __restrict__ bhh,
                      const float* __restrict__ bsh,
                      float* __restrict__ out)
{
    extern __shared__ char smem[];
    __shared__ float sBias[192];
    __shared__ __align__(8) unsigned long long sMbarAW[3];
    __shared__ __align__(8) unsigned long long sMbarS[2];
    __shared__ __align__(8) unsigned long long sMbarE[3];

    const int tid  = threadIdx.x;
    const int lane = tid & 31;
    const int wid  = tid >> 5;
    const int warp_m = wid & 1;      // 2 m-warps * 32 rows
    const int warp_n = wid >> 1;     // 6 n-warps * 32 cols (warp_n == gate)
    const int jt = blockIdx.x;
    const int mt = blockIdx.y;       // 64-row tiles (1024)
    const int j0 = jt * 32;
    const int m0 = mt * BM;
    const int mt128 = mt >> 1;
    const int half  = mt & 1;        // which 64-row half of the 128-row gmem tile

    if (tid < 192) {
        const int g = tid >> 5, j = tid & 31, jj = j0 + j;
        float b = bih[g * DH + jj];
        b += (g < 4) ? bhh[g * DH + jj] : bsh[(g - 4) * DH + jj];
        sBias[tid] = b;
    }
    if (tid == 0) {
        #pragma unroll
        for (int i = 0; i < 3; ++i)
            asm volatile("mbarrier.init.shared.b64 [%0], 1;"
                         :: "r"(sm_u32(&sMbarAW[i])) : "memory");
        #pragma unroll
        for (int i = 0; i < 2; ++i)
            asm volatile("mbarrier.init.shared.b64 [%0], 1;"
                         :: "r"(sm_u32(&sMbarS[i])) : "memory");
        #pragma unroll
        for (int i = 0; i < 3; ++i)
            asm volatile("mbarrier.init.shared.b64 [%0], %1;"
                         :: "r"(sm_u32(&sMbarE[i])), "r"((unsigned)THREADS) : "memory");
        asm volatile("fence.proxy.async.shared::cta;" ::: "memory");
    }
    __syncthreads();

    const unsigned mbAW[3] = { sm_u32(&sMbarAW[0]), sm_u32(&sMbarAW[1]), sm_u32(&sMbarAW[2]) };
    const unsigned mbS[2]  = { sm_u32(&sMbarS[0]), sm_u32(&sMbarS[1]) };
    const unsigned mbE[3]  = { sm_u32(&sMbarE[0]), sm_u32(&sMbarE[1]), sm_u32(&sMbarE[2]) };

    float acc[2][4][4];
    #pragma unroll
    for (int a = 0; a < 2; ++a)
        #pragma unroll
        for (int b = 0; b < 4; ++b)
            #pragma unroll
            for (int d = 0; d < 4; ++d) acc[a][b][d] = 0.0f;

    // ---- stage A+W for one chunk (3-deep ring) ----
    auto stage_aw = [&](int ch) {
        char* buf = smem + (ch % 3) * AW_STRIDE;
        const unsigned mb = mbAW[ch % 3];
        asm volatile("mbarrier.arrive.expect_tx.shared.b64 _, [%0], %1;"
                     :: "r"(mb), "r"(32768u) : "memory");
        bulkN(buf,         g_xh2 + (size_t)(mt128 * 8 + ch) * 1024 + half * 512, 8192u, mb);
        bulkN(buf + OFF_W, g_w2  + (size_t)(jt * 8 + ch) * 1536, 24576u, mb);
    };
    // ---- stage S for chunk sch+4 (2-deep ring) ----
    auto stage_s = [&](int sch) {
        char* buf = smem + OFF_S + (sch & 1) * 8192;
        const unsigned mb = mbS[sch & 1];
        asm volatile("mbarrier.arrive.expect_tx.shared.b64 _, [%0], %1;"
                     :: "r"(mb), "r"(8192u) : "memory");
        bulkN(buf, g_s2 + (size_t)(mt128 * 4 + sch) * 1024 + half * 512, 8192u, mb);
    };

    // ---- mma over one K chunk (4 x k16), warp tile 32m x 32n ----
    const int arow = lane & 15;
    const int ak8  = (lane >> 4) & 1;
    const int brow8 = ((lane >> 4) << 3) + (lane & 7);
    const int bk8  = (lane >> 3) & 1;

    auto mma_chunk = [&](int ch) {
        const char* aw = smem + (ch % 3) * AW_STRIDE;
        const char* A = (ch >= 4 && warp_n >= 4)
                      ? smem + OFF_S + ((ch - 4) & 1) * 8192
                      : aw;
        const char* W = aw + OFF_W;
        #pragma unroll
        for (int kq = 0; kq < 4; ++kq) {
            unsigned a0[4], a1[4];
            {
                const int r0 = warp_m * 32 + arow;
                const int r1 = r0 + 16;
                const int g = kq * 2 + ak8;
                ldsm4(a0, A + r0 * 128 + ((g ^ (r0 & 7)) << 4));
                ldsm4(a1, A + r1 * 128 + ((g ^ (r1 & 7)) << 4));
            }
            unsigned bb[2][4];
            #pragma unroll
            for (int nf2 = 0; nf2 < 2; ++nf2) {
                const int r = warp_n * 32 + nf2 * 16 + brow8;
                const int g = kq * 2 + bk8;
                ldsm4(bb[nf2], W + r * 128 + ((g ^ (r & 7)) << 4));
            }
            #pragma unroll
            for (int nf2 = 0; nf2 < 2; ++nf2) {
                mma16816(acc[0][nf2 * 2    ], a0, bb[nf2][0], bb[nf2][1]);
                mma16816(acc[0][nf2 * 2 + 1], a0, bb[nf2][2], bb[nf2][3]);
                mma16816(acc[1][nf2 * 2    ], a1, bb[nf2][0], bb[nf2][1]);
                mma16816(acc[1][nf2 * 2 + 1], a1, bb[nf2][2], bb[nf2][3]);
            }
        }
    };

    // ---- free-running producer/consumer mainloop (no __syncthreads) ----
    if (tid == 0) { stage_aw(0); stage_aw(1); }
    int phAW0 = 0, phAW1 = 0, phAW2 = 0;
    int phS0 = 0, phS1 = 0;
    int phE0 = 0, phE1 = 0, phE2 = 0;
    #pragma unroll
    for (int ch = 0; ch < NCH; ++ch) {
        const int b = ch % 3;
        if (b == 0)      { mbar_wait(mbAW[0], phAW0); phAW0 ^= 1; }
        else if (b == 1) { mbar_wait(mbAW[1], phAW1); phAW1 ^= 1; }
        else             { mbar_wait(mbAW[2], phAW2); phAW2 ^= 1; }
        if (ch >= 4) {
            if ((ch - 4) & 1) { mbar_wait(mbS[1], phS1); phS1 ^= 1; }
            else              { mbar_wait(mbS[0], phS0); phS0 ^= 1; }
        }
        if (tid == 0) {
            const bool doAW = (ch + 2 < NCH);
            const bool doS  = (ch >= 3 && ch + 1 < NCH);
            if (doAW || doS) {
                if (ch >= 1) {   // wait for all readers of chunk ch-1 (slot (ch+2)%3)
                    const int e = (ch + 2) % 3;
                    if (e == 0)      { mbar_wait(mbE[0], phE0); phE0 ^= 1; }
                    else if (e == 1) { mbar_wait(mbE[1], phE1); phE1 ^= 1; }
                    else             { mbar_wait(mbE[2], phE2); phE2 ^= 1; }
                }
                if (doAW) stage_aw(ch + 2);
                if (doS)  stage_s(ch + 1 - 4);
            }
        }
        mma_chunk(ch);
        mbar_arrive(mbE[ch % 3]);   // done reading chunk ch
    }
    __syncthreads();

    // ---- epilogue: accums -> smem so each thread sees all 6 gates ----
    float* zs = (float*)smem;   // [64][193]
    const int q  = lane >> 2;
    const int cq = lane & 3;
    #pragma unroll
    for (int mf = 0; mf < 2; ++mf)
        #pragma unroll
        for (int nf = 0; nf < 4; ++nf) {
            const int row = warp_m * 32 + mf * 16 + q;
            const int col = warp_n * 32 + nf * 8 + 2 * cq;
            zs[(row    ) * 193 + col    ] = acc[mf][nf][0];
            zs[(row    ) * 193 + col + 1] = acc[mf][nf][1];
            zs[(row + 8) * 193 + col    ] = acc[mf][nf][2];
            zs[(row + 8) * 193 + col + 1] = acc[mf][nf][3];
        }
    __syncthreads();

    const size_t PLANE = (size_t)B_TOT * DH;
    for (int e = tid; e < BM * 32; e += THREADS) {
        const int m = e >> 5;
        const int j = e & 31;
        const int n = m0 + m;
        const int jj = j0 + j;
        const float* zrow = zs + (size_t)m * 193;
        const float zi  = zrow[      j] + sBias[      j];
        const float zf  = zrow[ 32 + j] + sBias[ 32 + j];
        const float zo  = zrow[ 64 + j] + sBias[ 64 + j];
        const float zc  = zrow[ 96 + j] + sBias[ 96 + j];
        const float zb0 = zrow[128 + j] + sBias[128 + j];
        const float zb1 = zrow[160 + j] + sBias[160 + j];

        const float ig  = sigmoidf_(zi);
        const float fg  = sigmoidf_(zf);
        const float og  = sigmoidf_(zo);
        const float bg0 = sigmoidf_(zb0);
        const float bg1 = sigmoidf_(zb1);

        const float mval = mask[n];
        const float cold = cm[(size_t)n * DH + jj];
        const float ct = (fg * cold + ig * tanhf(zc)) * mval;
        const float tc = tanhf(ct) * mval;

        const size_t base = (size_t)n * DH + jj;
        out[base            ] = og  * tc;
        out[PLANE     + base] = ct;
        out[2 * PLANE + base] = bg0 * tc;
        out[3 * PLANE + base] = bg1 * tc;
    }
}

extern "C" void kernel_launch(void* const* d_in, const int* in_sizes, int n_in,
                              void* d_out, int out_size) {
    (void)in_sizes; (void)n_in; (void)out_size;
    const float* x    = (const float*)d_in[0];
    const float* hm   = (const float*)d_in[1];
    const float* cm   = (const float*)d_in[2];
    const float* sm   = (const float*)d_in[3];
    const float* mask = (const float*)d_in[4];
    const float* wih  = (const float*)d_in[5];
    const float* whh  = (const float*)d_in[6];
    const float* wsh  = (const float*)d_in[7];
    const float* bih  = (const float*)d_in[8];
    const float* bhh  = (const float*)d_in[9];
    const float* bsh  = (const float*)d_in[10];
    const int*   idx  = (const int*)d_in[11];
    float* out = (float*)d_out;

    cvt_all_kernel<<<4096, 256>>>(x, hm, sm, idx, wih, whh, wsh);

    cudaFuncSetAttribute(lstm_gemm_kernel,
                         cudaFuncAttributeMaxDynamicSharedMemorySize, SMEM_BYTES);
    dim3 grid(DH / 32, B_TOT / BM);   // (8, 1024): j fast -> activation reuse in L2
    lstm_gemm_kernel<<<grid, THREADS, SMEM_BYTES>>>(cm, mask, bih, bhh, bsh, out);
}